// round 3
// baseline (speedup 1.0000x reference)
#include <cuda_runtime.h>
#include <math_constants.h>

#define AA 68                 // total action dim (3+3+4+25+25+8)
#define ROWS_PER_BLOCK 64
#define THREADS 64
#define ROW_PAD 69            // 69 mod 32 = 5, coprime -> conflict-free per-thread smem row reads
#define MAX_BLOCKS 16384

__device__ float g_partials[MAX_BLOCKS];
__device__ int   g_count = 0;
__device__ unsigned int g_total_blocks;   // unused placeholder (kept simple: passed as arg)

__global__ void kl_fused_kernel(const float* __restrict__ cur,
                                const float* __restrict__ prev,
                                float* __restrict__ out,
                                int W, int nb, float inv_w)
{
    __shared__ float tile[ROWS_PER_BLOCK * ROW_PAD];
    __shared__ float xs[AA];
    __shared__ float red2[2];
    __shared__ int   s_rank;

    const int tid  = threadIdx.x;
    const int row0 = blockIdx.x * ROWS_PER_BLOCK;

    const int   seg_off[7] = {0, 3, 6, 10, 35, 60, AA};
    const float inv_n[6]   = {1.f/3.f, 1.f/3.f, 0.25f, 0.04f, 0.04f, 0.125f};

    // --- segmented log_softmax of current_action (tiny; 6 threads, 1 segment each)
    if (tid < 6) {
        const int s = seg_off[tid], e = seg_off[tid + 1];
        float m = -CUDART_INF_F;
        for (int i = s; i < e; i++) m = fmaxf(m, cur[i]);
        float S = 0.f;
        for (int i = s; i < e; i++) S += __expf(cur[i] - m);
        const float lse = m + __logf(S);
        for (int i = s; i < e; i++) xs[i] = cur[i] - lse;
    }

    // --- stage tile: coalesced float4 global loads, scalar smem stores (padded rows)
    const int rows_here = min(ROWS_PER_BLOCK, W - row0);
    const float4* gsrc = reinterpret_cast<const float4*>(prev + (size_t)row0 * AA);
    if (rows_here == ROWS_PER_BLOCK) {
        // full tile: 64*17 = 1088 float4, 17 per thread, fully unrolled for MLP
        #pragma unroll
        for (int k = 0; k < (ROWS_PER_BLOCK * (AA / 4)) / THREADS; k++) {
            const int i = tid + k * THREADS;
            float4 v = gsrc[i];
            const int r = i / (AA / 4);
            const int c = (i % (AA / 4)) * 4;
            float* dst = &tile[r * ROW_PAD + c];
            dst[0] = v.x; dst[1] = v.y; dst[2] = v.z; dst[3] = v.w;
        }
    } else if (rows_here > 0) {
        const int nv4 = rows_here * (AA / 4);
        for (int i = tid; i < nv4; i += THREADS) {
            float4 v = gsrc[i];
            const int r = i / (AA / 4);
            const int c = (i % (AA / 4)) * 4;
            float* dst = &tile[r * ROW_PAD + c];
            dst[0] = v.x; dst[1] = v.y; dst[2] = v.z; dst[3] = v.w;
        }
    }
    __syncthreads();

    // --- per-thread row reduction (2 passes per segment, all from smem/registers)
    float acc = 0.f;
    if (tid < rows_here) {
        const float* row = &tile[tid * ROW_PAD];
        #pragma unroll
        for (int j = 0; j < 6; j++) {
            const int s = seg_off[j], e = seg_off[j + 1];
            float m = -CUDART_INF_F;
            for (int i = s; i < e; i++) m = fmaxf(m, row[i]);
            float S = 0.f, T = 0.f, U = 0.f;
            for (int i = s; i < e; i++) {
                const float z  = row[i] - m;
                const float ez = __expf(z);
                S += ez;
                T = fmaf(ez, z, T);
                U = fmaf(ez, xs[i], U);
            }
            // sum_i p_i*(t_i - x_i) = (T - U)/S - log S   with t = z - m - logS
            acc += inv_n[j] * ((T - U) * (1.f / S) - __logf(S));
        }
    }

    // --- block reduction (2 warps) -> one deterministic partial per block
    #pragma unroll
    for (int o = 16; o; o >>= 1) acc += __shfl_xor_sync(0xffffffffu, acc, o);
    if ((tid & 31) == 0) red2[tid >> 5] = acc;
    __syncthreads();
    if (tid == 0) g_partials[blockIdx.x] = red2[0] + red2[1];

    // --- last-arriving block performs the deterministic final sum
    __threadfence();
    if (tid == 0) s_rank = atomicAdd(&g_count, 1);
    __syncthreads();
    if (s_rank == nb - 1) {
        float s = 0.f;
        for (int i = tid; i < nb; i += THREADS) s += __ldcg(&g_partials[i]);
        #pragma unroll
        for (int o = 16; o; o >>= 1) s += __shfl_xor_sync(0xffffffffu, s, o);
        if ((tid & 31) == 0) red2[tid >> 5] = s;
        __syncthreads();
        if (tid == 0) {
            out[0] = (red2[0] + red2[1]) * inv_w;
            g_count = 0;               // reset for next graph replay
        }
    }
}

extern "C" void kernel_launch(void* const* d_in, const int* in_sizes, int n_in,
                              void* d_out, int out_size)
{
    const float* cur  = (const float*)d_in[0];   // [68]
    const float* prev = (const float*)d_in[1];   // [W, 68]
    float* out = (float*)d_out;

    const int W  = in_sizes[1] / AA;
    int nb = (W + ROWS_PER_BLOCK - 1) / ROWS_PER_BLOCK;
    if (nb > MAX_BLOCKS) nb = MAX_BLOCKS;        // W=524288 -> 8192 blocks

    kl_fused_kernel<<<nb, THREADS>>>(cur, prev, out, W, nb, 1.0f / (float)W);
}

// round 5
// speedup vs baseline: 1.3579x; 1.3579x over previous
#include <cuda_runtime.h>
#include <math_constants.h>

#define AA 68                 // total action dim (3+3+4+25+25+8)
#define NF4 17                // float4 per row
#define ROWS_PER_BLOCK 128
#define THREADS 128
#define MAX_BLOCKS 16384

__device__ float g_partials[MAX_BLOCKS];
__device__ int   g_count = 0;

__device__ __forceinline__ constexpr int seg_of(int i) {
    return i < 3 ? 0 : i < 6 ? 1 : i < 10 ? 2 : i < 35 ? 3 : i < 60 ? 4 : 5;
}

__global__ __launch_bounds__(THREADS)
void kl_fused_kernel(const float* __restrict__ cur,
                     const float* __restrict__ prev,
                     float* __restrict__ out,
                     int W, int nb, float inv_w)
{
    __shared__ float4 tile4[ROWS_PER_BLOCK * NF4];   // 34816 B, linear layout == global
    __shared__ float  xs[AA];
    __shared__ float  redw[THREADS / 32];
    __shared__ int    s_rank;

    const int tid  = threadIdx.x;
    const int row0 = blockIdx.x * ROWS_PER_BLOCK;

    // --- segmented log_softmax of current_action (tiny; 6 threads, 1 segment each)
    if (tid < 6) {
        const int seg_off[7] = {0, 3, 6, 10, 35, 60, AA};
        const int s = seg_off[tid], e = seg_off[tid + 1];
        float m = -CUDART_INF_F;
        for (int i = s; i < e; i++) m = fmaxf(m, cur[i]);
        float S = 0.f;
        for (int i = s; i < e; i++) S += __expf(cur[i] - m);
        const float lse = m + __logf(S);
        for (int i = s; i < e; i++) xs[i] = cur[i] - lse;
    }

    // --- stage tile: coalesced float4 LDG -> STS.128 (conflict-free, linear)
    const int rows_here = min(ROWS_PER_BLOCK, W - row0);
    const float4* gsrc = reinterpret_cast<const float4*>(prev + (size_t)row0 * AA);
    if (rows_here == ROWS_PER_BLOCK) {
        #pragma unroll 4
        for (int k = 0; k < NF4; k++) {
            const int i = k * THREADS + tid;
            tile4[i] = gsrc[i];
        }
    } else if (rows_here > 0) {
        const int nv4 = rows_here * NF4;
        for (int i = tid; i < nv4; i += THREADS) tile4[i] = gsrc[i];
    }
    __syncthreads();

    // --- per-thread row: one-pass segmented softmax-KL, LDS.128 conflict-free
    float acc = 0.f;
    if (tid < rows_here) {
        const float4* row4 = &tile4[tid * NF4];
        float S[6], T[6], U[6];
        #pragma unroll
        for (int j = 0; j < 6; j++) { S[j] = 0.f; T[j] = 0.f; U[j] = 0.f; }

        #pragma unroll
        for (int c4 = 0; c4 < NF4; c4++) {
            const float4 v = row4[c4];
            const float elem[4] = {v.x, v.y, v.z, v.w};
            #pragma unroll
            for (int k = 0; k < 4; k++) {
                const int idx = 4 * c4 + k;      // compile-time constant
                const int j   = seg_of(idx);     // folds to immediate
                const float x  = elem[k];
                const float ex = __expf(x);
                S[j] += ex;
                T[j] = fmaf(ex, x, T[j]);
                U[j] = fmaf(ex, xs[idx], U[j]);  // LDS broadcast
            }
        }
        const float inv_n[6] = {1.f/3.f, 1.f/3.f, 0.25f, 0.04f, 0.04f, 0.125f};
        #pragma unroll
        for (int j = 0; j < 6; j++)
            acc += inv_n[j] * ((T[j] - U[j]) * (1.f / S[j]) - __logf(S[j]));
    }

    // --- block reduction -> deterministic partial per block
    #pragma unroll
    for (int o = 16; o; o >>= 1) acc += __shfl_xor_sync(0xffffffffu, acc, o);
    if ((tid & 31) == 0) redw[tid >> 5] = acc;
    __syncthreads();
    if (tid == 0) {
        float s = 0.f;
        #pragma unroll
        for (int w = 0; w < THREADS / 32; w++) s += redw[w];
        g_partials[blockIdx.x] = s;
        // release: orders the g_partials store before the counter bump (no L1 flush)
        int old;
        asm volatile("atom.add.acq_rel.gpu.global.s32 %0, [%1], 1;"
                     : "=r"(old) : "l"(&g_count) : "memory");
        s_rank = old;
    }
    __syncthreads();

    // --- last-arriving block: deterministic final sum (fixed index order)
    if (s_rank == nb - 1) {
        float s = 0.f;
        for (int i = tid; i < nb; i += THREADS) s += __ldcg(&g_partials[i]);
        #pragma unroll
        for (int o = 16; o; o >>= 1) s += __shfl_xor_sync(0xffffffffu, s, o);
        if ((tid & 31) == 0) redw[tid >> 5] = s;
        __syncthreads();
        if (tid == 0) {
            float t = 0.f;
            #pragma unroll
            for (int w = 0; w < THREADS / 32; w++) t += redw[w];
            out[0] = t * inv_w;
            g_count = 0;                      // reset for next graph replay
        }
    }
}

extern "C" void kernel_launch(void* const* d_in, const int* in_sizes, int n_in,
                              void* d_out, int out_size)
{
    const float* cur  = (const float*)d_in[0];   // [68]
    const float* prev = (const float*)d_in[1];   // [W, 68]
    float* out = (float*)d_out;

    const int W  = in_sizes[1] / AA;
    int nb = (W + ROWS_PER_BLOCK - 1) / ROWS_PER_BLOCK;
    if (nb > MAX_BLOCKS) nb = MAX_BLOCKS;        // W=524288 -> 4096 blocks

    kl_fused_kernel<<<nb, THREADS>>>(cur, prev, out, W, nb, 1.0f / (float)W);
}

// round 6
// speedup vs baseline: 2.3628x; 1.7401x over previous
#include <cuda_runtime.h>
#include <math_constants.h>

#define AA 68                  // total action dim (3+3+4+25+25+8)
#define NF4 17                 // float4 per row
#define TILE_ROWS 64
#define THREADS 64
#define TILE_F4 (TILE_ROWS * NF4)   // 1088 float4 = 17408 B per buffer
#define GRID_MAX 888                // 148 SM * 6 blocks/SM

__device__ float g_partials[GRID_MAX];
__device__ int   g_count = 0;

__device__ __forceinline__ void cpa16(void* dst_smem, const void* src_gmem) {
    unsigned d = (unsigned)__cvta_generic_to_shared(dst_smem);
    asm volatile("cp.async.cg.shared.global [%0], [%1], 16;" :: "r"(d), "l"(src_gmem));
}
#define CP_COMMIT()  asm volatile("cp.async.commit_group;")
#define CP_WAIT(n)   asm volatile("cp.async.wait_group %0;" :: "n"(n))

__device__ __forceinline__ constexpr int seg_of(int i) {
    return i < 3 ? 0 : i < 6 ? 1 : i < 10 ? 2 : i < 35 ? 3 : i < 60 ? 4 : 5;
}

__global__ __launch_bounds__(THREADS)
void kl_pipe_kernel(const float* __restrict__ cur,
                    const float* __restrict__ prev,
                    float* __restrict__ out,
                    int W, int n_tiles, int grid_n, float inv_w)
{
    __shared__ float4 buf[2][TILE_F4];   // 34816 B double buffer
    __shared__ float  xs[AA];
    __shared__ float  redw[THREADS / 32];
    __shared__ int    s_rank;

    const int tid = threadIdx.x;
    const int bid = blockIdx.x;

    // --- segmented log_softmax of current_action (once per block)
    if (tid < 6) {
        const int seg_off[7] = {0, 3, 6, 10, 35, 60, AA};
        const int s = seg_off[tid], e = seg_off[tid + 1];
        float m = -CUDART_INF_F;
        for (int i = s; i < e; i++) m = fmaxf(m, cur[i]);
        float S = 0.f;
        for (int i = s; i < e; i++) S += __expf(cur[i] - m);
        const float lse = m + __logf(S);
        for (int i = s; i < e; i++) xs[i] = cur[i] - lse;
    }

    const float4* src4 = reinterpret_cast<const float4*>(prev);

    // --- prologue: prefetch first tile
    const int t0 = bid;
    if (t0 < n_tiles) {
        const int nv4 = min(TILE_F4, (W - t0 * TILE_ROWS) * NF4);
        if (nv4 == TILE_F4) {
            #pragma unroll
            for (int k = 0; k < TILE_F4 / THREADS; k++) {
                const int i = k * THREADS + tid;
                cpa16(&buf[0][i], &src4[(size_t)t0 * TILE_F4 + i]);
            }
        } else {
            for (int i = tid; i < nv4; i += THREADS)
                cpa16(&buf[0][i], &src4[(size_t)t0 * TILE_F4 + i]);
        }
        CP_COMMIT();
    }

    // --- pipelined mainloop: prefetch t+grid while computing t
    float acc = 0.f;
    int k = 0;
    for (int t = t0; t < n_tiles; t += grid_n, ++k) {
        const int tn = t + grid_n;
        if (tn < n_tiles) {
            float4* nbuf = buf[(k + 1) & 1];
            const int nv4 = min(TILE_F4, (W - tn * TILE_ROWS) * NF4);
            if (nv4 == TILE_F4) {
                #pragma unroll
                for (int q = 0; q < TILE_F4 / THREADS; q++) {
                    const int i = q * THREADS + tid;
                    cpa16(&nbuf[i], &src4[(size_t)tn * TILE_F4 + i]);
                }
            } else {
                for (int i = tid; i < nv4; i += THREADS)
                    cpa16(&nbuf[i], &src4[(size_t)tn * TILE_F4 + i]);
            }
            CP_COMMIT();
            CP_WAIT(1);          // oldest group (tile t) complete
        } else {
            CP_WAIT(0);
        }
        __syncthreads();         // tile t visible to all threads

        const int rows_here = min(TILE_ROWS, W - t * TILE_ROWS);
        if (tid < rows_here) {
            const float4* row4 = &buf[k & 1][tid * NF4];
            float S[6], T[6], U[6];
            #pragma unroll
            for (int j = 0; j < 6; j++) { S[j] = 0.f; T[j] = 0.f; U[j] = 0.f; }

            #pragma unroll
            for (int c4 = 0; c4 < NF4; c4++) {
                const float4 v = row4[c4];
                const float elem[4] = {v.x, v.y, v.z, v.w};
                #pragma unroll
                for (int e = 0; e < 4; e++) {
                    const int idx = 4 * c4 + e;    // compile-time constant
                    const int j   = seg_of(idx);   // folds to immediate
                    const float x  = elem[e];
                    const float ex = __expf(x);    // one-pass: inputs are O(1), fp32-safe
                    S[j] += ex;
                    T[j] = fmaf(ex, x, T[j]);
                    U[j] = fmaf(ex, xs[idx], U[j]);
                }
            }
            const float inv_n[6] = {1.f/3.f, 1.f/3.f, 0.25f, 0.04f, 0.04f, 0.125f};
            #pragma unroll
            for (int j = 0; j < 6; j++)
                acc += inv_n[j] * ((T[j] - U[j]) * (1.f / S[j]) - __logf(S[j]));
        }
        __syncthreads();         // all reads of buf[k&1] done before it is refilled at k+2
    }

    // --- block reduction -> deterministic per-block partial
    #pragma unroll
    for (int o = 16; o; o >>= 1) acc += __shfl_xor_sync(0xffffffffu, acc, o);
    if ((tid & 31) == 0) redw[tid >> 5] = acc;
    __syncthreads();
    if (tid == 0) {
        float s = 0.f;
        #pragma unroll
        for (int w = 0; w < THREADS / 32; w++) s += redw[w];
        g_partials[bid] = s;
        int old;
        asm volatile("atom.add.acq_rel.gpu.global.s32 %0, [%1], 1;"
                     : "=r"(old) : "l"(&g_count) : "memory");
        s_rank = old;
    }
    __syncthreads();

    // --- last-arriving block: deterministic final sum (fixed index order)
    if (s_rank == grid_n - 1) {
        float s = 0.f;
        for (int i = tid; i < grid_n; i += THREADS) s += __ldcg(&g_partials[i]);
        #pragma unroll
        for (int o = 16; o; o >>= 1) s += __shfl_xor_sync(0xffffffffu, s, o);
        if ((tid & 31) == 0) redw[tid >> 5] = s;
        __syncthreads();
        if (tid == 0) {
            float t = 0.f;
            #pragma unroll
            for (int w = 0; w < THREADS / 32; w++) t += redw[w];
            out[0] = t * inv_w;
            g_count = 0;                  // reset for next graph replay
        }
    }
}

extern "C" void kernel_launch(void* const* d_in, const int* in_sizes, int n_in,
                              void* d_out, int out_size)
{
    const float* cur  = (const float*)d_in[0];   // [68]
    const float* prev = (const float*)d_in[1];   // [W, 68]
    float* out = (float*)d_out;

    const int W = in_sizes[1] / AA;
    const int n_tiles = (W + TILE_ROWS - 1) / TILE_ROWS;   // 8192 for W=524288
    int grid_n = GRID_MAX;
    if (grid_n > n_tiles) grid_n = n_tiles;

    kl_pipe_kernel<<<grid_n, THREADS>>>(cur, prev, out, W, n_tiles, grid_n, 1.0f / (float)W);
}